// round 3
// baseline (speedup 1.0000x reference)
#include <cuda_runtime.h>
#include <cuda_bf16.h>
#include <stdint.h>

#define MAX_N 100000
#define MAX_E 1600000
#define IN_DIM 128
#define HID 64
#define LAT 32

typedef unsigned long long ull;

// ---------------- device scratch (zero-at-entry invariants) ----------------
// g_deg, g_cnt: 0 at entry; reset inside k_scan_lb after consumption.
// g_cursor: 0 at entry; reset in k_prop (first call).
// g_tile_state: 0 at entry; reset in k_fill (after scan consumed it).
__device__ float g_deg[MAX_N];
__device__ float g_dinv[MAX_N];
__device__ int   g_cnt[MAX_N];
__device__ int   g_rowptr[MAX_N + 1];
__device__ int   g_cursor[MAX_N];
__device__ ull   g_cv[MAX_E];           // packed (col | val<<32)
__device__ ull   g_tile_state[128];     // decoupled-lookback states
__device__ float g_xw[(size_t)MAX_N * HID];
__device__ float g_h[(size_t)MAX_N * HID];
__device__ float g_h2[(size_t)MAX_N * HID];

// ---------------- packed f32x2 helpers ----------------
__device__ __forceinline__ void fma2(ull& c, ull a, ull b) {
    asm("fma.rn.f32x2 %0, %1, %2, %3;" : "=l"(c) : "l"(a), "l"(b), "l"(c));
}
__device__ __forceinline__ ull dup2(float a) {
    ull r; unsigned u = __float_as_uint(a);
    asm("mov.b64 %0, {%1, %1};" : "=l"(r) : "r"(u));
    return r;
}
__device__ __forceinline__ ull duphi(ull cv) {
    unsigned hi = (unsigned)(cv >> 32);
    ull r;
    asm("mov.b64 %0, {%1, %1};" : "=l"(r) : "r"(hi));
    return r;
}
__device__ __forceinline__ float2 unpack2(ull v) {
    unsigned lo, hi;
    asm("mov.b64 {%0, %1}, %2;" : "=r"(lo), "=r"(hi) : "l"(v));
    return make_float2(__uint_as_float(lo), __uint_as_float(hi));
}

// int64-vs-int32 edge_index detection (JAX x64-off downgrades int64->int32).
__device__ __forceinline__ int detect_is64(const void* ei) {
    const int* p = (const int*)ei;
    int is64 = 1;
#pragma unroll
    for (int i = 0; i < 16; i++) is64 &= (p[2 * i + 1] == 0);
    return is64;
}
__device__ __forceinline__ int get_idx(const void* ei, int is64, long long pos) {
    return is64 ? (int)((const long long*)ei)[pos] : ((const int*)ei)[pos];
}

// ---------------- K0: GEMM1 (xw = x @ W1) + grid-stride edge count tail ------
// 782 blocks, 256 thr; each block: 128-row x 64-col tile, thread tile 4x8;
// after epilogue, grid-stride over edges for deg/cnt atomics.
__global__ void k_gemm1count(const float* __restrict__ A, const float* __restrict__ W,
                             float* __restrict__ C, int M,
                             const void* __restrict__ ei, const float* __restrict__ ew,
                             int E) {
    __shared__ __align__(16) float Bs[IN_DIM * HID];   // 32KB
    __shared__ __align__(16) float Ast[32 * 128];      // 16KB

    int tid = threadIdx.x;
    int tx = tid & 7;
    int ty = tid >> 3;
    int row0 = blockIdx.x * 128;

    const float4* W4 = (const float4*)W;
    float4* Bs4 = (float4*)Bs;
    for (int t = tid; t < IN_DIM * HID / 4; t += 256) Bs4[t] = W4[t];

    ull acc[4][4] = {};
    const float4* A4 = (const float4*)A;

    for (int kh = 0; kh < 4; kh++) {
        __syncthreads();
        for (int t = tid; t < 1024; t += 256) {
            int r = t >> 3, k4 = t & 7;
            int gr = row0 + r;
            float4 a = (gr < M) ? A4[(size_t)gr * 32 + kh * 8 + k4]
                                : make_float4(0.f, 0.f, 0.f, 0.f);
            Ast[(4 * k4 + 0) * 128 + r] = a.x;
            Ast[(4 * k4 + 1) * 128 + r] = a.y;
            Ast[(4 * k4 + 2) * 128 + r] = a.z;
            Ast[(4 * k4 + 3) * 128 + r] = a.w;
        }
        __syncthreads();
#pragma unroll
        for (int k = 0; k < 32; k++) {
            float4 av = *(const float4*)(Ast + k * 128 + 4 * ty);
            const float* brow = Bs + (kh * 32 + k) * 64 + 8 * tx;
            ulonglong2 b01 = *(const ulonglong2*)brow;
            ulonglong2 b23 = *(const ulonglong2*)(brow + 4);
            ull a0 = dup2(av.x), a1 = dup2(av.y), a2 = dup2(av.z), a3 = dup2(av.w);
            fma2(acc[0][0], a0, b01.x); fma2(acc[0][1], a0, b01.y);
            fma2(acc[0][2], a0, b23.x); fma2(acc[0][3], a0, b23.y);
            fma2(acc[1][0], a1, b01.x); fma2(acc[1][1], a1, b01.y);
            fma2(acc[1][2], a1, b23.x); fma2(acc[1][3], a1, b23.y);
            fma2(acc[2][0], a2, b01.x); fma2(acc[2][1], a2, b01.y);
            fma2(acc[2][2], a2, b23.x); fma2(acc[2][3], a2, b23.y);
            fma2(acc[3][0], a3, b01.x); fma2(acc[3][1], a3, b01.y);
            fma2(acc[3][2], a3, b23.x); fma2(acc[3][3], a3, b23.y);
        }
    }
#pragma unroll
    for (int i = 0; i < 4; i++) {
        int gr = row0 + 4 * ty + i;
        if (gr < M) {
            float2* cp = (float2*)C + (size_t)gr * 32 + 4 * tx;
#pragma unroll
            for (int j = 0; j < 4; j++) cp[j] = unpack2(acc[i][j]);
        }
    }

    // ---- count tail: deg/cnt atomics over a grid-stride edge range ----
    int is64 = detect_is64(ei);
    long long stride = (long long)gridDim.x * blockDim.x;
    for (long long e = (long long)blockIdx.x * blockDim.x + tid; e < E; e += stride) {
        int d = get_idx(ei, is64, (long long)E + e);
        atomicAdd(&g_deg[d], ew[e]);
        atomicAdd(&g_cnt[d], 1);
    }
}

// ---------------- K1: single-pass decoupled-lookback scan + dinv ------------
// 1024 elements per 256-thread block (4/thread). Also: dinv = rsqrt(1+deg),
// resets deg and cnt (restore zero-at-entry invariant).
__global__ void k_scan_lb(int n, int nblocks) {
    const int b = blockIdx.x;
    const int t = threadIdx.x;
    const int i0 = b * 1024 + t * 4;

    int4 v;
    if (i0 + 3 < n) {
        v = *(const int4*)&g_cnt[i0];
        *(int4*)&g_cnt[i0] = make_int4(0, 0, 0, 0);
        float4 dg = *(const float4*)&g_deg[i0];
        float4 dv = make_float4(rsqrtf(1.f + dg.x), rsqrtf(1.f + dg.y),
                                rsqrtf(1.f + dg.z), rsqrtf(1.f + dg.w));
        *(float4*)&g_dinv[i0] = dv;
        *(float4*)&g_deg[i0] = make_float4(0.f, 0.f, 0.f, 0.f);
    } else {
        int vv[4];
#pragma unroll
        for (int q = 0; q < 4; q++) {
            int i = i0 + q;
            vv[q] = 0;
            if (i < n) {
                vv[q] = g_cnt[i];
                g_cnt[i] = 0;
                g_dinv[i] = rsqrtf(1.f + g_deg[i]);
                g_deg[i] = 0.f;
            }
        }
        v = make_int4(vv[0], vv[1], vv[2], vv[3]);
    }

    int tsum = v.x + v.y + v.z + v.w;
    int lane = t & 31, wid = t >> 5;
    int inc = tsum;
#pragma unroll
    for (int off = 1; off < 32; off <<= 1) {
        int o = __shfl_up_sync(0xffffffffu, inc, off);
        if (lane >= off) inc += o;
    }
    __shared__ int wsum[8];
    __shared__ int s_prefix;
    __shared__ int s_total;
    if (lane == 31) wsum[wid] = inc;
    __syncthreads();
    if (t == 0) {
        int a = 0;
#pragma unroll
        for (int w2 = 0; w2 < 8; w2++) { int tmp = wsum[w2]; wsum[w2] = a; a += tmp; }
        s_total = a;
        // publish + lookback
        if (b == 0) {
            atomicExch(&g_tile_state[0], ((ull)2 << 32) | (unsigned)a);
            s_prefix = 0;
        } else {
            atomicExch(&g_tile_state[b], ((ull)1 << 32) | (unsigned)a);
            int excl = 0;
            int p = b - 1;
            while (true) {
                ull s = *(volatile ull*)&g_tile_state[p];
                unsigned flag = (unsigned)(s >> 32);
                if (flag == 0) continue;
                excl += (int)(unsigned)s;
                if (flag == 2) break;
                p--;
            }
            atomicExch(&g_tile_state[b], ((ull)2 << 32) | (unsigned)(excl + a));
            s_prefix = excl;
        }
    }
    __syncthreads();

    int e0 = s_prefix + wsum[wid] + (inc - tsum);
    if (i0 + 3 < n) {
        *(int4*)&g_rowptr[i0] = make_int4(e0, e0 + v.x, e0 + v.x + v.y,
                                          e0 + v.x + v.y + v.z);
    } else {
        if (i0 < n)     g_rowptr[i0]     = e0;
        if (i0 + 1 < n) g_rowptr[i0 + 1] = e0 + v.x;
        if (i0 + 2 < n) g_rowptr[i0 + 2] = e0 + v.x + v.y;
        if (i0 + 3 < n) g_rowptr[i0 + 3] = e0 + v.x + v.y + v.z;
    }
    if (b == nblocks - 1 && t == 0) g_rowptr[n] = s_prefix + s_total;
}

// ---------------- K2: fill CSR (packed col|val), reset tile states ----------
__global__ void k_fill(const void* __restrict__ ei, const float* __restrict__ ew, int E) {
    if (blockIdx.x == 0 && threadIdx.x < 128) g_tile_state[threadIdx.x] = 0;
    __shared__ int flag;
    if (threadIdx.x == 0) flag = detect_is64(ei);
    __syncthreads();
    int is64 = flag;
    int e = blockIdx.x * blockDim.x + threadIdx.x;
    if (e < E) {
        int s = get_idx(ei, is64, e);
        int d = get_idx(ei, is64, (long long)E + e);
        int pos = g_rowptr[d] + atomicAdd(&g_cursor[d], 1);
        float v = g_dinv[s] * ew[e] * g_dinv[d];
        g_cv[pos] = (ull)(unsigned)s | ((ull)__float_as_uint(v) << 32);
    }
}

// ---------------- K3/K4: propagation (warp per dst, lane owns dim pair) -----
__global__ void k_prop(const float* __restrict__ in, float* __restrict__ out,
                       const float* __restrict__ bias, int relu, int n,
                       int resetCursor) {
    int w = (blockIdx.x * blockDim.x + threadIdx.x) >> 5;
    int lane = threadIdx.x & 31;
    if (w >= n) return;
    if (resetCursor && lane == 0) g_cursor[w] = 0;

    float di = g_dinv[w];
    ull acc0 = 0, acc1 = 0;
    {
        ull self = ((const ull*)in)[(size_t)w * 32 + lane];
        fma2(acc0, dup2(di * di), self);
    }
    int s = g_rowptr[w];
    int e = g_rowptr[w + 1];
    int j = s;
    for (; j + 4 <= e; j += 4) {
        ull cv0 = g_cv[j + 0];
        ull cv1 = g_cv[j + 1];
        ull cv2 = g_cv[j + 2];
        ull cv3 = g_cv[j + 3];
        ull p0 = ((const ull*)in)[(size_t)(unsigned)cv0 * 32 + lane];
        ull p1 = ((const ull*)in)[(size_t)(unsigned)cv1 * 32 + lane];
        ull p2 = ((const ull*)in)[(size_t)(unsigned)cv2 * 32 + lane];
        ull p3 = ((const ull*)in)[(size_t)(unsigned)cv3 * 32 + lane];
        fma2(acc0, duphi(cv0), p0);
        fma2(acc1, duphi(cv1), p1);
        fma2(acc0, duphi(cv2), p2);
        fma2(acc1, duphi(cv3), p3);
    }
    for (; j < e; j++) {
        ull cv = g_cv[j];
        ull p = ((const ull*)in)[(size_t)(unsigned)cv * 32 + lane];
        fma2(acc0, duphi(cv), p);
    }
    float2 r0 = unpack2(acc0);
    float2 r1 = unpack2(acc1);
    float2 r = make_float2(r0.x + r1.x, r0.y + r1.y);
    if (bias) { float2 bb = ((const float2*)bias)[lane]; r.x += bb.x; r.y += bb.y; }
    if (relu) { r.x = fmaxf(r.x, 0.0f); r.y = fmaxf(r.y, 0.0f); }
    ((float2*)out)[(size_t)w * 32 + lane] = r;
}

// ---------------- K5: GEMM2: [mu|lv] = h2[M,64] @ [Wmu|Wlv] + bias ----------
__global__ void k_gemm2(const float* __restrict__ A,
                        const float* __restrict__ Wmu, const float* __restrict__ Wlv,
                        const float* __restrict__ bmu, const float* __restrict__ blv,
                        float* __restrict__ Omu, float* __restrict__ Olv, int M) {
    __shared__ __align__(16) float Bs[HID * 64];
    __shared__ __align__(16) float Ast[32 * 128];
    int tid = threadIdx.x;
    int tx = tid & 7, ty = tid >> 3;
    int row0 = blockIdx.x * 128;

    {
        const float4* Wm4 = (const float4*)Wmu;
        const float4* Wl4 = (const float4*)Wlv;
        float4* Bs4 = (float4*)Bs;
        for (int t = tid; t < HID * 64 / 4; t += 256) {
            int k = t >> 4;
            int c4 = t & 15;
            Bs4[t] = (c4 < 8) ? Wm4[k * 8 + c4] : Wl4[k * 8 + (c4 - 8)];
        }
    }

    ull acc[4][4] = {};
    const float4* A4 = (const float4*)A;
    for (int kh = 0; kh < 2; kh++) {
        __syncthreads();
        for (int t = tid; t < 1024; t += 256) {
            int r = t >> 3, k4 = t & 7;
            int gr = row0 + r;
            float4 a = (gr < M) ? A4[(size_t)gr * 16 + kh * 8 + k4]
                                : make_float4(0.f, 0.f, 0.f, 0.f);
            Ast[(4 * k4 + 0) * 128 + r] = a.x;
            Ast[(4 * k4 + 1) * 128 + r] = a.y;
            Ast[(4 * k4 + 2) * 128 + r] = a.z;
            Ast[(4 * k4 + 3) * 128 + r] = a.w;
        }
        __syncthreads();
#pragma unroll
        for (int k = 0; k < 32; k++) {
            float4 av = *(const float4*)(Ast + k * 128 + 4 * ty);
            const float* brow = Bs + (kh * 32 + k) * 64 + 8 * tx;
            ulonglong2 b01 = *(const ulonglong2*)brow;
            ulonglong2 b23 = *(const ulonglong2*)(brow + 4);
            ull a0 = dup2(av.x), a1 = dup2(av.y), a2 = dup2(av.z), a3 = dup2(av.w);
            fma2(acc[0][0], a0, b01.x); fma2(acc[0][1], a0, b01.y);
            fma2(acc[0][2], a0, b23.x); fma2(acc[0][3], a0, b23.y);
            fma2(acc[1][0], a1, b01.x); fma2(acc[1][1], a1, b01.y);
            fma2(acc[1][2], a1, b23.x); fma2(acc[1][3], a1, b23.y);
            fma2(acc[2][0], a2, b01.x); fma2(acc[2][1], a2, b01.y);
            fma2(acc[2][2], a2, b23.x); fma2(acc[2][3], a2, b23.y);
            fma2(acc[3][0], a3, b01.x); fma2(acc[3][1], a3, b01.y);
            fma2(acc[3][2], a3, b23.x); fma2(acc[3][3], a3, b23.y);
        }
    }

    int isMu = (tx < 4);
    const float2* bsrc = (const float2*)(isMu ? bmu : blv);
    float2* osrc = (float2*)(isMu ? Omu : Olv);
    int cpBase = isMu ? (4 * tx) : (4 * tx - 16);
#pragma unroll
    for (int i = 0; i < 4; i++) {
        int gr = row0 + 4 * ty + i;
        if (gr < M) {
#pragma unroll
            for (int j = 0; j < 4; j++) {
                float2 r = unpack2(acc[i][j]);
                float2 bb = bsrc[cpBase + j];
                r.x += bb.x; r.y += bb.y;
                osrc[(size_t)gr * 16 + cpBase + j] = r;
            }
        }
    }
}

// ---------------- launch ----------------
extern "C" void kernel_launch(void* const* d_in, const int* in_sizes, int n_in,
                              void* d_out, int out_size) {
    const float* x   = (const float*)d_in[0];
    const void*  ei  = d_in[1];
    const float* ew  = (const float*)d_in[2];
    const float* W1  = (const float*)d_in[3];
    const float* b1  = (const float*)d_in[4];
    const float* Wmu = (const float*)d_in[5];
    const float* bmu = (const float*)d_in[6];
    const float* Wlv = (const float*)d_in[7];
    const float* blv = (const float*)d_in[8];

    int N = in_sizes[0] / IN_DIM;
    int E = in_sizes[2];
    float* outp = (float*)d_out;
    float* Omu = outp;
    float* Olv = outp + (size_t)N * LAT;

    float *d_xw, *d_h, *d_h2;
    cudaGetSymbolAddress((void**)&d_xw, g_xw);
    cudaGetSymbolAddress((void**)&d_h, g_h);
    cudaGetSymbolAddress((void**)&d_h2, g_h2);

    int GB = (N + 127) / 128;
    int nbE = (E + 255) / 256;
    int nbScan = (N + 1023) / 1024;
    int nbP = (N + 7) / 8;

    k_gemm1count<<<GB, 256>>>(x, W1, d_xw, N, ei, ew, E);     // launch 0
    k_scan_lb<<<nbScan, 256>>>(N, nbScan);                     // launch 1
    k_fill<<<nbE, 256>>>(ei, ew, E);                           // launch 2
    k_prop<<<nbP, 256>>>(d_xw, d_h, b1, 1, N, 1);              // launch 3 (profiled)
    k_prop<<<nbP, 256>>>(d_h, d_h2, nullptr, 0, N, 0);         // launch 4
    k_gemm2<<<GB, 256>>>(d_h2, Wmu, Wlv, bmu, blv, Omu, Olv, N); // launch 5
}